// round 1
// baseline (speedup 1.0000x reference)
#include <cuda_runtime.h>
#include <cuda_bf16.h>

#define BB 8
#define CC 256
#define HW 1024
#define HEADS 8
#define HD 32
#define NG 8
#define GS 32  // channels per group

// Scratch (allocation-guard safe)
__device__ float g_h[BB * CC * HW];        // group-normed activations [B, C, N]
__device__ float g_qkv[BB * 3 * CC * HW];  // qkv [B, 3C, N]
__device__ float g_ao[BB * CC * HW];       // attention output [B, C, N]

// ---------------------------------------------------------------------------
// Kernel 1: GroupNorm. One block per (b, g). 32 ch x 1024 spatial = 32768 elems.
// ---------------------------------------------------------------------------
__global__ __launch_bounds__(256) void gn_kernel(const float* __restrict__ x,
                                                 const float* __restrict__ sc,
                                                 const float* __restrict__ bi) {
    const int b = blockIdx.x / NG;
    const int g = blockIdx.x % NG;
    const int NE = GS * HW;  // 32768
    const float* xp = x + ((size_t)b * CC + g * GS) * HW;
    float* hp = g_h + ((size_t)b * CC + g * GS) * HW;

    float s = 0.f, s2 = 0.f;
    const float4* x4 = (const float4*)xp;
    for (int i = threadIdx.x; i < NE / 4; i += 256) {
        float4 v = x4[i];
        s += v.x + v.y + v.z + v.w;
        s2 += v.x * v.x + v.y * v.y + v.z * v.z + v.w * v.w;
    }
    __shared__ float rs[256], rs2[256];
    rs[threadIdx.x] = s; rs2[threadIdx.x] = s2;
    __syncthreads();
    for (int o = 128; o > 0; o >>= 1) {
        if (threadIdx.x < o) {
            rs[threadIdx.x] += rs[threadIdx.x + o];
            rs2[threadIdx.x] += rs2[threadIdx.x + o];
        }
        __syncthreads();
    }
    const float mean = rs[0] / NE;
    const float var = rs2[0] / NE - mean * mean;
    const float rstd = rsqrtf(var + 1e-5f);

    float4* h4 = (float4*)hp;
    for (int i = threadIdx.x; i < NE / 4; i += 256) {
        const int c = g * GS + (i >> 8);  // 256 float4 per channel row
        const float a = sc[c] * rstd;
        const float d = bi[c] - mean * a;
        float4 v = x4[i];
        float4 o4;
        o4.x = v.x * a + d; o4.y = v.y * a + d;
        o4.z = v.z * a + d; o4.w = v.w * a + d;
        h4[i] = o4;
    }
}

// ---------------------------------------------------------------------------
// Kernel 2/4: batched GEMM  C[b] = A[M,K] @ Bmat[b][K,HW] + bias (+ residual)
// 64x64 tiles, 16x16 threads, 4x4 micro-tile (stride-16 mapping).
// ---------------------------------------------------------------------------
template <int M_TOTAL, bool RESID>
__global__ __launch_bounds__(256) void gemm_kernel(const float* __restrict__ A,
                                                   const float* __restrict__ bias,
                                                   const float* __restrict__ Bmat,
                                                   const float* __restrict__ resid,
                                                   float* __restrict__ Cout) {
    const int bb = blockIdx.z;
    const int m0 = blockIdx.y * 64;
    const int n0 = blockIdx.x * 64;
    const float* Bp = Bmat + (size_t)bb * CC * HW;
    float* Cp = Cout + (size_t)bb * M_TOTAL * HW;
    const float* Rp = RESID ? (resid + (size_t)bb * M_TOTAL * HW) : nullptr;

    __shared__ float As[16][64];
    __shared__ float Bs[16][64];

    const int tid = threadIdx.x;
    const int tx = tid & 15;
    const int ty = tid >> 4;

    float acc[4][4];
#pragma unroll
    for (int i = 0; i < 4; i++)
#pragma unroll
        for (int j = 0; j < 4; j++) acc[i][j] = 0.f;

    for (int k0 = 0; k0 < CC; k0 += 16) {
#pragma unroll
        for (int r = 0; r < 4; r++) {
            const int id = tid + r * 256;
            const int mi = id >> 4, ki = id & 15;
            As[ki][mi] = A[(size_t)(m0 + mi) * CC + k0 + ki];
            const int ni = id & 63, kj = id >> 6;
            Bs[kj][ni] = Bp[(size_t)(k0 + kj) * HW + n0 + ni];
        }
        __syncthreads();
#pragma unroll
        for (int kk = 0; kk < 16; kk++) {
            float a[4], bv[4];
#pragma unroll
            for (int u = 0; u < 4; u++) {
                a[u] = As[kk][ty + u * 16];
                bv[u] = Bs[kk][tx + u * 16];
            }
#pragma unroll
            for (int i = 0; i < 4; i++)
#pragma unroll
                for (int j = 0; j < 4; j++) acc[i][j] += a[i] * bv[j];
        }
        __syncthreads();
    }

#pragma unroll
    for (int i = 0; i < 4; i++) {
        const int m = m0 + ty + i * 16;
        const float bm = bias[m];
#pragma unroll
        for (int j = 0; j < 4; j++) {
            const int n = n0 + tx + j * 16;
            float v = acc[i][j] + bm;
            if (RESID) v += Rp[(size_t)m * HW + n];
            Cp[(size_t)m * HW + n] = v;
        }
    }
}

// ---------------------------------------------------------------------------
// Kernel 3: flash attention. grid = B*HEADS*4 (q-tiles of 256), 256 threads,
// one query per thread. K/V streamed through smem in 128-wide chunks.
// ---------------------------------------------------------------------------
__global__ __launch_bounds__(256, 2) void attn_kernel() {
    const int blk = blockIdx.x;
    const int qt = blk & 3;
    const int bh = blk >> 2;
    const int b = bh / HEADS;
    const int h = bh % HEADS;
    const int n = qt * 256 + threadIdx.x;

    const float* base = g_qkv + (size_t)b * 3 * CC * HW;
    const float* qp = base + (size_t)(h * HD) * HW + n;
    const float* kp = base + (size_t)(CC + h * HD) * HW;
    const float* vp = base + (size_t)(2 * CC + h * HD) * HW;

    const float scale = 0.17677669529663687f;  // 1/sqrt(32)
    float q[HD];
#pragma unroll
    for (int d = 0; d < HD; d++) q[d] = qp[(size_t)d * HW] * scale;

    float acc[HD];
#pragma unroll
    for (int d = 0; d < HD; d++) acc[d] = 0.f;
    float mrun = -1e30f, l = 0.f;

    __shared__ float sK[HD][128];
    __shared__ float sV[HD][128];

    for (int m0 = 0; m0 < HW; m0 += 128) {
        __syncthreads();
        for (int i = threadIdx.x; i < HD * 128; i += 256) {
            const int d = i >> 7, m = i & 127;
            sK[d][m] = kp[(size_t)d * HW + m0 + m];
            sV[d][m] = vp[(size_t)d * HW + m0 + m];
        }
        __syncthreads();

        for (int sub = 0; sub < 128; sub += 32) {
            float s[32];
#pragma unroll
            for (int m = 0; m < 32; m++) {
                float t = 0.f;
#pragma unroll
                for (int d = 0; d < HD; d++) t += q[d] * sK[d][sub + m];
                s[m] = t;
            }
            float cmax = mrun;
#pragma unroll
            for (int m = 0; m < 32; m++) cmax = fmaxf(cmax, s[m]);
            const float alpha = __expf(mrun - cmax);
            l *= alpha;
#pragma unroll
            for (int d = 0; d < HD; d++) acc[d] *= alpha;
            mrun = cmax;
#pragma unroll
            for (int m = 0; m < 32; m++) {
                const float p = __expf(s[m] - cmax);
                l += p;
#pragma unroll
                for (int d = 0; d < HD; d++) acc[d] += p * sV[d][sub + m];
            }
        }
    }

    const float inv = 1.f / l;
    float* op = g_ao + ((size_t)b * CC + h * HD) * HW + n;
#pragma unroll
    for (int d = 0; d < HD; d++) op[(size_t)d * HW] = acc[d] * inv;
}

// ---------------------------------------------------------------------------
extern "C" void kernel_launch(void* const* d_in, const int* in_sizes, int n_in,
                              void* d_out, int out_size) {
    const float* x = (const float*)d_in[0];
    const float* gn_scale = (const float*)d_in[1];
    const float* gn_bias = (const float*)d_in[2];
    const float* w_qkv = (const float*)d_in[3];
    const float* b_qkv = (const float*)d_in[4];
    const float* w_out = (const float*)d_in[5];
    const float* b_out = (const float*)d_in[6];
    float* out = (float*)d_out;

    float* hbuf;   cudaGetSymbolAddress((void**)&hbuf, g_h);
    float* qkv;    cudaGetSymbolAddress((void**)&qkv, g_qkv);
    float* ao;     cudaGetSymbolAddress((void**)&ao, g_ao);

    // 1) GroupNorm
    gn_kernel<<<BB * NG, 256>>>(x, gn_scale, gn_bias);

    // 2) QKV projection: [768,256] @ [256,1024] per batch
    {
        dim3 grid(HW / 64, (3 * CC) / 64, BB);
        gemm_kernel<3 * CC, false><<<grid, 256>>>(w_qkv, b_qkv, hbuf, nullptr, qkv);
    }

    // 3) Attention
    attn_kernel<<<BB * HEADS * 4, 256>>>();

    // 4) Output projection + residual
    {
        dim3 grid(HW / 64, CC / 64, BB);
        gemm_kernel<CC, true><<<grid, 256>>>(w_out, b_out, ao, x, out);
    }
}

// round 4
// speedup vs baseline: 1.3606x; 1.3606x over previous
#include <cuda_runtime.h>
#include <cuda_bf16.h>
#include <mma.h>

using namespace nvcuda;

#define BB 8
#define CC 256
#define HW 1024
#define HEADS 8
#define HD 32
#define NG 8
#define GS 32

__device__ __align__(256) float g_h[BB * CC * HW];
__device__ __align__(256) float g_qkv[BB * 3 * CC * HW];
__device__ __align__(256) float g_ao[BB * CC * HW];

// ---------------------------------------------------------------------------
// Kernel 1: GroupNorm (validated Round 1)
// ---------------------------------------------------------------------------
__global__ __launch_bounds__(256) void gn_kernel(const float* __restrict__ x,
                                                 const float* __restrict__ sc,
                                                 const float* __restrict__ bi) {
    const int b = blockIdx.x / NG;
    const int g = blockIdx.x % NG;
    const int NE = GS * HW;
    const float* xp = x + ((size_t)b * CC + g * GS) * HW;
    float* hp = g_h + ((size_t)b * CC + g * GS) * HW;

    float s = 0.f, s2 = 0.f;
    const float4* x4 = (const float4*)xp;
    for (int i = threadIdx.x; i < NE / 4; i += 256) {
        float4 v = x4[i];
        s += v.x + v.y + v.z + v.w;
        s2 += v.x * v.x + v.y * v.y + v.z * v.z + v.w * v.w;
    }
    __shared__ float rs[256], rs2[256];
    rs[threadIdx.x] = s; rs2[threadIdx.x] = s2;
    __syncthreads();
    for (int o = 128; o > 0; o >>= 1) {
        if (threadIdx.x < o) {
            rs[threadIdx.x] += rs[threadIdx.x + o];
            rs2[threadIdx.x] += rs2[threadIdx.x + o];
        }
        __syncthreads();
    }
    const float mean = rs[0] / NE;
    const float var = rs2[0] / NE - mean * mean;
    const float rstd = rsqrtf(var + 1e-5f);

    float4* h4 = (float4*)hp;
    for (int i = threadIdx.x; i < NE / 4; i += 256) {
        const int c = g * GS + (i >> 8);
        const float a = sc[c] * rstd;
        const float d = bi[c] - mean * a;
        float4 v = x4[i];
        float4 o4;
        o4.x = v.x * a + d; o4.y = v.y * a + d;
        o4.z = v.z * a + d; o4.w = v.w * a + d;
        h4[i] = o4;
    }
}

// ---------------------------------------------------------------------------
// Kernel 2/4: WMMA TF32 GEMM  C[b] = A[M,K] @ B[b][K,HW] + bias (+ residual)
// 64x64 block tile, 128 threads (4 warps, each 32x32 via 2x2 m16n16k8 frags).
// All fragment addressing is compiler-managed (wmma API).
// ---------------------------------------------------------------------------
template <int M_TOTAL, bool RESID>
__global__ __launch_bounds__(128) void gemm_wmma(const float* __restrict__ A,
                                                 const float* __restrict__ bias,
                                                 const float* __restrict__ Bmat,
                                                 const float* __restrict__ resid,
                                                 float* __restrict__ Cout) {
    const int bb = blockIdx.z;
    const int m0 = blockIdx.y * 64;
    const int n0 = blockIdx.x * 64;
    const float* Bp = Bmat + (size_t)bb * CC * HW;
    float* Cp = Cout + (size_t)bb * M_TOTAL * HW;
    const float* Rp = RESID ? (resid + (size_t)bb * M_TOTAL * HW) : nullptr;

    // ldm values (24, 72, 36 floats) are all multiples of 16 bytes.
    __shared__ __align__(128) float As[64][24];   // [m][k] tile
    __shared__ __align__(128) float Bs[16][72];   // [k][n] tile
    __shared__ __align__(128) float Cs[4][32][36];  // per-warp 32x32 result

    const int tid = threadIdx.x;
    const int w = tid >> 5;
    const int wm = (w >> 1) * 32;
    const int wn = (w & 1) * 32;

    wmma::fragment<wmma::accumulator, 16, 16, 8, float> fc[2][2];
#pragma unroll
    for (int i = 0; i < 2; i++)
#pragma unroll
        for (int j = 0; j < 2; j++) wmma::fill_fragment(fc[i][j], 0.0f);

    for (int k0 = 0; k0 < CC; k0 += 16) {
        // Stage gmem -> regs (2 float4 each for A and B), then regs -> smem.
        float4 av[2], bv[2];
#pragma unroll
        for (int t = 0; t < 2; t++) {
            const int ida = tid + t * 128;                 // 256 float4 = 64x16
            av[t] = *(const float4*)(A + (size_t)(m0 + (ida >> 2)) * CC + k0 + (ida & 3) * 4);
            const int idb = tid + t * 128;                 // 256 float4 = 16x64
            bv[t] = *(const float4*)(Bp + (size_t)(k0 + (idb >> 4)) * HW + n0 + (idb & 15) * 4);
        }
        __syncthreads();
#pragma unroll
        for (int t = 0; t < 2; t++) {
            const int ida = tid + t * 128;
            float* ap = &As[ida >> 2][(ida & 3) * 4];
            ap[0] = wmma::__float_to_tf32(av[t].x);
            ap[1] = wmma::__float_to_tf32(av[t].y);
            ap[2] = wmma::__float_to_tf32(av[t].z);
            ap[3] = wmma::__float_to_tf32(av[t].w);
            const int idb = tid + t * 128;
            float* bp = &Bs[idb >> 4][(idb & 15) * 4];
            bp[0] = wmma::__float_to_tf32(bv[t].x);
            bp[1] = wmma::__float_to_tf32(bv[t].y);
            bp[2] = wmma::__float_to_tf32(bv[t].z);
            bp[3] = wmma::__float_to_tf32(bv[t].w);
        }
        __syncthreads();

#pragma unroll
        for (int ks = 0; ks < 2; ks++) {
            wmma::fragment<wmma::matrix_a, 16, 16, 8, wmma::precision::tf32, wmma::row_major> fa[2];
            wmma::fragment<wmma::matrix_b, 16, 16, 8, wmma::precision::tf32, wmma::row_major> fb[2];
#pragma unroll
            for (int i = 0; i < 2; i++)
                wmma::load_matrix_sync(fa[i], &As[wm + i * 16][ks * 8], 24);
#pragma unroll
            for (int j = 0; j < 2; j++)
                wmma::load_matrix_sync(fb[j], &Bs[ks * 8][wn + j * 16], 72);
#pragma unroll
            for (int i = 0; i < 2; i++)
#pragma unroll
                for (int j = 0; j < 2; j++)
                    wmma::mma_sync(fc[i][j], fa[i], fb[j], fc[i][j]);
        }
    }

    __syncthreads();
#pragma unroll
    for (int i = 0; i < 2; i++)
#pragma unroll
        for (int j = 0; j < 2; j++)
            wmma::store_matrix_sync(&Cs[w][i * 16][j * 16], fc[i][j], 36, wmma::mem_row_major);
    __syncthreads();

    // Fused epilogue: bias (+ residual), float4 stores. 64x64 = 1024 float4.
#pragma unroll
    for (int t = 0; t < 8; t++) {
        const int id = tid + t * 128;
        const int r = id >> 4;
        const int c4 = (id & 15) * 4;
        const int wq = ((r >> 5) << 1) | (c4 >> 5);
        const float* cp = &Cs[wq][r & 31][c4 & 31];
        float4 v = *(const float4*)cp;
        const float bm = bias[m0 + r];
        v.x += bm; v.y += bm; v.z += bm; v.w += bm;
        if (RESID) {
            float4 rv = *(const float4*)(Rp + (size_t)(m0 + r) * HW + n0 + c4);
            v.x += rv.x; v.y += rv.y; v.z += rv.z; v.w += rv.w;
        }
        *(float4*)(Cp + (size_t)(m0 + r) * HW + n0 + c4) = v;
    }
}

// ---------------------------------------------------------------------------
// Kernel 3: scalar flash attention (validated Round 1)
// ---------------------------------------------------------------------------
__global__ __launch_bounds__(256, 2) void attn_kernel() {
    const int blk = blockIdx.x;
    const int qt = blk & 3;
    const int bh = blk >> 2;
    const int b = bh / HEADS;
    const int h = bh % HEADS;
    const int n = qt * 256 + threadIdx.x;

    const float* base = g_qkv + (size_t)b * 3 * CC * HW;
    const float* qp = base + (size_t)(h * HD) * HW + n;
    const float* kp = base + (size_t)(CC + h * HD) * HW;
    const float* vp = base + (size_t)(2 * CC + h * HD) * HW;

    const float scale = 0.17677669529663687f;
    float q[HD];
#pragma unroll
    for (int d = 0; d < HD; d++) q[d] = qp[(size_t)d * HW] * scale;

    float acc[HD];
#pragma unroll
    for (int d = 0; d < HD; d++) acc[d] = 0.f;
    float mrun = -1e30f, l = 0.f;

    __shared__ float sK[HD][128];
    __shared__ float sV[HD][128];

    for (int m0 = 0; m0 < HW; m0 += 128) {
        __syncthreads();
        for (int i = threadIdx.x; i < HD * 128; i += 256) {
            const int d = i >> 7, m = i & 127;
            sK[d][m] = kp[(size_t)d * HW + m0 + m];
            sV[d][m] = vp[(size_t)d * HW + m0 + m];
        }
        __syncthreads();

        for (int sub = 0; sub < 128; sub += 32) {
            float s[32];
#pragma unroll
            for (int m = 0; m < 32; m++) {
                float t = 0.f;
#pragma unroll
                for (int d = 0; d < HD; d++) t += q[d] * sK[d][sub + m];
                s[m] = t;
            }
            float cmax = mrun;
#pragma unroll
            for (int m = 0; m < 32; m++) cmax = fmaxf(cmax, s[m]);
            const float alpha = __expf(mrun - cmax);
            l *= alpha;
#pragma unroll
            for (int d = 0; d < HD; d++) acc[d] *= alpha;
            mrun = cmax;
#pragma unroll
            for (int m = 0; m < 32; m++) {
                const float p = __expf(s[m] - cmax);
                l += p;
#pragma unroll
                for (int d = 0; d < HD; d++) acc[d] += p * sV[d][sub + m];
            }
        }
    }

    const float inv = 1.f / l;
    float* op = g_ao + ((size_t)b * CC + h * HD) * HW + n;
#pragma unroll
    for (int d = 0; d < HD; d++) op[(size_t)d * HW] = acc[d] * inv;
}

// ---------------------------------------------------------------------------
extern "C" void kernel_launch(void* const* d_in, const int* in_sizes, int n_in,
                              void* d_out, int out_size) {
    const float* x = (const float*)d_in[0];
    const float* gn_scale = (const float*)d_in[1];
    const float* gn_bias = (const float*)d_in[2];
    const float* w_qkv = (const float*)d_in[3];
    const float* b_qkv = (const float*)d_in[4];
    const float* w_out = (const float*)d_in[5];
    const float* b_out = (const float*)d_in[6];
    float* out = (float*)d_out;

    float* hbuf; cudaGetSymbolAddress((void**)&hbuf, g_h);
    float* qkv;  cudaGetSymbolAddress((void**)&qkv, g_qkv);
    float* ao;   cudaGetSymbolAddress((void**)&ao, g_ao);

    gn_kernel<<<BB * NG, 256>>>(x, gn_scale, gn_bias);

    {
        dim3 grid(HW / 64, (3 * CC) / 64, BB);
        gemm_wmma<3 * CC, false><<<grid, 128>>>(w_qkv, b_qkv, hbuf, nullptr, qkv);
    }

    attn_kernel<<<BB * HEADS * 4, 256>>>();

    {
        dim3 grid(HW / 64, CC / 64, BB);
        gemm_wmma<CC, true><<<grid, 128>>>(w_out, b_out, ao, x, out);
    }
}

// round 5
// speedup vs baseline: 1.8297x; 1.3447x over previous
#include <cuda_runtime.h>
#include <cuda_bf16.h>
#include <mma.h>

using namespace nvcuda;

#define BB 8
#define CC 256
#define HW 1024
#define HEADS 8
#define HD 32
#define NG 8
#define GS 32

__device__ __align__(256) float g_h[BB * CC * HW];
__device__ __align__(256) float g_qkv[BB * 3 * CC * HW];
__device__ __align__(256) float g_ao[BB * CC * HW];

// ---------------------------------------------------------------------------
// Kernel 1: GroupNorm (validated)
// ---------------------------------------------------------------------------
__global__ __launch_bounds__(256) void gn_kernel(const float* __restrict__ x,
                                                 const float* __restrict__ sc,
                                                 const float* __restrict__ bi) {
    const int b = blockIdx.x / NG;
    const int g = blockIdx.x % NG;
    const int NE = GS * HW;
    const float* xp = x + ((size_t)b * CC + g * GS) * HW;
    float* hp = g_h + ((size_t)b * CC + g * GS) * HW;

    float s = 0.f, s2 = 0.f;
    const float4* x4 = (const float4*)xp;
    for (int i = threadIdx.x; i < NE / 4; i += 256) {
        float4 v = x4[i];
        s += v.x + v.y + v.z + v.w;
        s2 += v.x * v.x + v.y * v.y + v.z * v.z + v.w * v.w;
    }
    __shared__ float rs[256], rs2[256];
    rs[threadIdx.x] = s; rs2[threadIdx.x] = s2;
    __syncthreads();
    for (int o = 128; o > 0; o >>= 1) {
        if (threadIdx.x < o) {
            rs[threadIdx.x] += rs[threadIdx.x + o];
            rs2[threadIdx.x] += rs2[threadIdx.x + o];
        }
        __syncthreads();
    }
    const float mean = rs[0] / NE;
    const float var = rs2[0] / NE - mean * mean;
    const float rstd = rsqrtf(var + 1e-5f);

    float4* h4 = (float4*)hp;
    for (int i = threadIdx.x; i < NE / 4; i += 256) {
        const int c = g * GS + (i >> 8);
        const float a = sc[c] * rstd;
        const float d = bi[c] - mean * a;
        float4 v = x4[i];
        float4 o4;
        o4.x = v.x * a + d; o4.y = v.y * a + d;
        o4.z = v.z * a + d; o4.w = v.w * a + d;
        h4[i] = o4;
    }
}

// ---------------------------------------------------------------------------
// Kernel 2/4: WMMA TF32 GEMM (validated)
// ---------------------------------------------------------------------------
template <int M_TOTAL, bool RESID>
__global__ __launch_bounds__(128) void gemm_wmma(const float* __restrict__ A,
                                                 const float* __restrict__ bias,
                                                 const float* __restrict__ Bmat,
                                                 const float* __restrict__ resid,
                                                 float* __restrict__ Cout) {
    const int bb = blockIdx.z;
    const int m0 = blockIdx.y * 64;
    const int n0 = blockIdx.x * 64;
    const float* Bp = Bmat + (size_t)bb * CC * HW;
    float* Cp = Cout + (size_t)bb * M_TOTAL * HW;
    const float* Rp = RESID ? (resid + (size_t)bb * M_TOTAL * HW) : nullptr;

    __shared__ __align__(128) float As[64][24];
    __shared__ __align__(128) float Bs[16][72];
    __shared__ __align__(128) float Cs[4][32][36];

    const int tid = threadIdx.x;
    const int w = tid >> 5;
    const int wm = (w >> 1) * 32;
    const int wn = (w & 1) * 32;

    wmma::fragment<wmma::accumulator, 16, 16, 8, float> fc[2][2];
#pragma unroll
    for (int i = 0; i < 2; i++)
#pragma unroll
        for (int j = 0; j < 2; j++) wmma::fill_fragment(fc[i][j], 0.0f);

    for (int k0 = 0; k0 < CC; k0 += 16) {
        float4 av[2], bv[2];
#pragma unroll
        for (int t = 0; t < 2; t++) {
            const int ida = tid + t * 128;
            av[t] = *(const float4*)(A + (size_t)(m0 + (ida >> 2)) * CC + k0 + (ida & 3) * 4);
            const int idb = tid + t * 128;
            bv[t] = *(const float4*)(Bp + (size_t)(k0 + (idb >> 4)) * HW + n0 + (idb & 15) * 4);
        }
        __syncthreads();
#pragma unroll
        for (int t = 0; t < 2; t++) {
            const int ida = tid + t * 128;
            float* ap = &As[ida >> 2][(ida & 3) * 4];
            ap[0] = wmma::__float_to_tf32(av[t].x);
            ap[1] = wmma::__float_to_tf32(av[t].y);
            ap[2] = wmma::__float_to_tf32(av[t].z);
            ap[3] = wmma::__float_to_tf32(av[t].w);
            const int idb = tid + t * 128;
            float* bp = &Bs[idb >> 4][(idb & 15) * 4];
            bp[0] = wmma::__float_to_tf32(bv[t].x);
            bp[1] = wmma::__float_to_tf32(bv[t].y);
            bp[2] = wmma::__float_to_tf32(bv[t].z);
            bp[3] = wmma::__float_to_tf32(bv[t].w);
        }
        __syncthreads();

#pragma unroll
        for (int ks = 0; ks < 2; ks++) {
            wmma::fragment<wmma::matrix_a, 16, 16, 8, wmma::precision::tf32, wmma::row_major> fa[2];
            wmma::fragment<wmma::matrix_b, 16, 16, 8, wmma::precision::tf32, wmma::row_major> fb[2];
#pragma unroll
            for (int i = 0; i < 2; i++)
                wmma::load_matrix_sync(fa[i], &As[wm + i * 16][ks * 8], 24);
#pragma unroll
            for (int j = 0; j < 2; j++)
                wmma::load_matrix_sync(fb[j], &Bs[ks * 8][wn + j * 16], 72);
#pragma unroll
            for (int i = 0; i < 2; i++)
#pragma unroll
                for (int j = 0; j < 2; j++)
                    wmma::mma_sync(fc[i][j], fa[i], fb[j], fc[i][j]);
        }
    }

    __syncthreads();
#pragma unroll
    for (int i = 0; i < 2; i++)
#pragma unroll
        for (int j = 0; j < 2; j++)
            wmma::store_matrix_sync(&Cs[w][i * 16][j * 16], fc[i][j], 36, wmma::mem_row_major);
    __syncthreads();

#pragma unroll
    for (int t = 0; t < 8; t++) {
        const int id = tid + t * 128;
        const int r = id >> 4;
        const int c4 = (id & 15) * 4;
        const int wq = ((r >> 5) << 1) | (c4 >> 5);
        const float* cp = &Cs[wq][r & 31][c4 & 31];
        float4 v = *(const float4*)cp;
        const float bm = bias[m0 + r];
        v.x += bm; v.y += bm; v.z += bm; v.w += bm;
        if (RESID) {
            float4 rv = *(const float4*)(Rp + (size_t)(m0 + r) * HW + n0 + c4);
            v.x += rv.x; v.y += rv.y; v.z += rv.z; v.w += rv.w;
        }
        *(float4*)(Cp + (size_t)(m0 + r) * HW + n0 + c4) = v;
    }
}

// ---------------------------------------------------------------------------
// Kernel 3: WMMA TF32 flash attention.
// Block = (b, h, 64-query tile), 128 threads / 4 warps (warp w owns q-rows
// [16w,16w+16)). Per 64-key chunk: S = Q*K (HMMA), softmax in smem
// (2 threads/row), running O in smem rescaled by alpha, O += P*V (HMMA).
// ---------------------------------------------------------------------------
__global__ __launch_bounds__(128) void attn_wmma() {
    const int qt = blockIdx.x & 15;
    const int bh = blockIdx.x >> 4;
    const int b = bh >> 3;
    const int h = bh & 7;
    const int n0q = qt * 64;

    const int tid = threadIdx.x;
    const int w = tid >> 5;

    const float* base = g_qkv + (size_t)b * 3 * CC * HW;
    const float* qp = base + (size_t)(h * HD) * HW;
    const float* kp = base + (size_t)(CC + h * HD) * HW;
    const float* vp = base + (size_t)(2 * CC + h * HD) * HW;

    __shared__ __align__(128) float Ss[64][72];  // Q staging, then S/P, then PV
    __shared__ __align__(128) float Ks[32][72];  // K chunk [d][key]
    __shared__ __align__(128) float Vs[32][72];  // V chunk [d][key] (= V^T col-major)
    __shared__ __align__(128) float Os[64][40];  // running output [q][d]

    const float scale = 0.17677669529663687f;  // 1/sqrt(32)

    // Stage Q transposed: Ss[q][d] = Q[d][n0q+q] * scale (coalesced along q).
    for (int i = tid; i < 64 * 32; i += 128) {
        const int d = i >> 6, q = i & 63;
        Ss[q][d] = wmma::__float_to_tf32(qp[(size_t)d * HW + n0q + q] * scale);
    }
    for (int i = tid; i < 64 * 40; i += 128) (&Os[0][0])[i] = 0.f;
    __syncthreads();

    // Q fragments live in registers for the whole kernel.
    wmma::fragment<wmma::matrix_a, 16, 16, 8, wmma::precision::tf32, wmma::row_major> fq[4];
#pragma unroll
    for (int ks = 0; ks < 4; ks++)
        wmma::load_matrix_sync(fq[ks], &Ss[w * 16][ks * 8], 72);
    __syncthreads();  // Ss is free for reuse now

    float m_run = -1e30f, l_run = 0.f;
    const int r = tid >> 1;       // softmax row owned (2 threads per row)
    const int half = tid & 1;     // which 32-col half

    for (int m0 = 0; m0 < HW; m0 += 64) {
        // ---- load K/V chunk: 32 d x 64 keys each ----
        for (int i = tid; i < 512; i += 128) {
            const int d = i >> 4, c4 = (i & 15) * 4;
            float4 kv = *(const float4*)(kp + (size_t)d * HW + m0 + c4);
            Ks[d][c4 + 0] = wmma::__float_to_tf32(kv.x);
            Ks[d][c4 + 1] = wmma::__float_to_tf32(kv.y);
            Ks[d][c4 + 2] = wmma::__float_to_tf32(kv.z);
            Ks[d][c4 + 3] = wmma::__float_to_tf32(kv.w);
            float4 vv = *(const float4*)(vp + (size_t)d * HW + m0 + c4);
            Vs[d][c4 + 0] = wmma::__float_to_tf32(vv.x);
            Vs[d][c4 + 1] = wmma::__float_to_tf32(vv.y);
            Vs[d][c4 + 2] = wmma::__float_to_tf32(vv.z);
            Vs[d][c4 + 3] = wmma::__float_to_tf32(vv.w);
        }
        __syncthreads();

        // ---- S = Q K : warp w computes rows [16w,16w+16) x 64 cols ----
        {
            wmma::fragment<wmma::accumulator, 16, 16, 8, float> sacc[4];
#pragma unroll
            for (int n = 0; n < 4; n++) wmma::fill_fragment(sacc[n], 0.0f);
#pragma unroll
            for (int ks = 0; ks < 4; ks++) {
#pragma unroll
                for (int n = 0; n < 4; n++) {
                    wmma::fragment<wmma::matrix_b, 16, 16, 8, wmma::precision::tf32, wmma::row_major> fb;
                    wmma::load_matrix_sync(fb, &Ks[ks * 8][n * 16], 72);
                    wmma::mma_sync(sacc[n], fq[ks], fb, sacc[n]);
                }
            }
#pragma unroll
            for (int n = 0; n < 4; n++)
                wmma::store_matrix_sync(&Ss[w * 16][n * 16], sacc[n], 72, wmma::mem_row_major);
        }
        __syncthreads();

        // ---- online softmax on Ss, rescale Os ----
        {
            float* srow = &Ss[r][half * 32];
            float4 sv[8];
#pragma unroll
            for (int j = 0; j < 8; j++) sv[j] = ((float4*)srow)[j];
            float mx = -1e30f;
#pragma unroll
            for (int j = 0; j < 8; j++)
                mx = fmaxf(mx, fmaxf(fmaxf(sv[j].x, sv[j].y), fmaxf(sv[j].z, sv[j].w)));
            mx = fmaxf(mx, __shfl_xor_sync(0xffffffffu, mx, 1));
            const float nm = fmaxf(m_run, mx);
            const float alpha = __expf(m_run - nm);
            float psum = 0.f;
#pragma unroll
            for (int j = 0; j < 8; j++) {
                sv[j].x = __expf(sv[j].x - nm);
                sv[j].y = __expf(sv[j].y - nm);
                sv[j].z = __expf(sv[j].z - nm);
                sv[j].w = __expf(sv[j].w - nm);
                psum += sv[j].x + sv[j].y + sv[j].z + sv[j].w;
                float4 o4;
                o4.x = wmma::__float_to_tf32(sv[j].x);
                o4.y = wmma::__float_to_tf32(sv[j].y);
                o4.z = wmma::__float_to_tf32(sv[j].z);
                o4.w = wmma::__float_to_tf32(sv[j].w);
                ((float4*)srow)[j] = o4;
            }
            psum += __shfl_xor_sync(0xffffffffu, psum, 1);
            l_run = l_run * alpha + psum;
            m_run = nm;
            float4* orow = (float4*)&Os[r][half * 16];
#pragma unroll
            for (int j = 0; j < 4; j++) {
                float4 v = orow[j];
                v.x *= alpha; v.y *= alpha; v.z *= alpha; v.w *= alpha;
                orow[j] = v;
            }
        }
        __syncthreads();

        // ---- PV: rows [16w,16w+16) x 32 d; A = P (row-major), B = V^T (col-major) ----
        {
            wmma::fragment<wmma::matrix_a, 16, 16, 8, wmma::precision::tf32, wmma::row_major> fp[8];
#pragma unroll
            for (int k = 0; k < 8; k++)
                wmma::load_matrix_sync(fp[k], &Ss[w * 16][k * 8], 72);
            wmma::fragment<wmma::accumulator, 16, 16, 8, float> oacc[2];
#pragma unroll
            for (int n = 0; n < 2; n++) wmma::fill_fragment(oacc[n], 0.0f);
#pragma unroll
            for (int k = 0; k < 8; k++) {
#pragma unroll
                for (int n = 0; n < 2; n++) {
                    wmma::fragment<wmma::matrix_b, 16, 16, 8, wmma::precision::tf32, wmma::col_major> fv;
                    wmma::load_matrix_sync(fv, &Vs[0][0] + n * 16 * 72 + k * 8, 72);
                    wmma::mma_sync(oacc[n], fp[k], fv, oacc[n]);
                }
            }
#pragma unroll
            for (int n = 0; n < 2; n++)
                wmma::store_matrix_sync(&Ss[w * 16][n * 16], oacc[n], 72, wmma::mem_row_major);
        }
        __syncthreads();

        // ---- Os += chunk PV (Ss cols 0..31) ----
        for (int i = tid; i < 64 * 32; i += 128) {
            const int rr = i >> 5, cc = i & 31;
            Os[rr][cc] += Ss[rr][cc];
        }
        // no sync needed: next loop writes Ks/Vs (disjoint), then syncs before
        // touching Ss again.
    }

    __syncthreads();
    // ---- finalize: out[d][q] = Os[q][d] / l ----
    const float inv = 1.f / l_run;
    float* aob = g_ao + ((size_t)b * CC + h * HD) * HW;
#pragma unroll
    for (int j = 0; j < 16; j++) {
        const int d = half * 16 + j;
        aob[(size_t)d * HW + n0q + r] = Os[r][d] * inv;
    }
}

// ---------------------------------------------------------------------------
extern "C" void kernel_launch(void* const* d_in, const int* in_sizes, int n_in,
                              void* d_out, int out_size) {
    const float* x = (const float*)d_in[0];
    const float* gn_scale = (const float*)d_in[1];
    const float* gn_bias = (const float*)d_in[2];
    const float* w_qkv = (const float*)d_in[3];
    const float* b_qkv = (const float*)d_in[4];
    const float* w_out = (const float*)d_in[5];
    const float* b_out = (const float*)d_in[6];
    float* out = (float*)d_out;

    float* hbuf; cudaGetSymbolAddress((void**)&hbuf, g_h);
    float* qkv;  cudaGetSymbolAddress((void**)&qkv, g_qkv);
    float* ao;   cudaGetSymbolAddress((void**)&ao, g_ao);

    gn_kernel<<<BB * NG, 256>>>(x, gn_scale, gn_bias);

    {
        dim3 grid(HW / 64, (3 * CC) / 64, BB);
        gemm_wmma<3 * CC, false><<<grid, 128>>>(w_qkv, b_qkv, hbuf, nullptr, qkv);
    }

    attn_wmma<<<BB * HEADS * 16, 128>>>();

    {
        dim3 grid(HW / 64, CC / 64, BB);
        gemm_wmma<CC, true><<<grid, 128>>>(w_out, b_out, ao, x, out);
    }
}

// round 6
// speedup vs baseline: 1.9316x; 1.0557x over previous
#include <cuda_runtime.h>
#include <cuda_bf16.h>
#include <mma.h>

using namespace nvcuda;

#define BB 8
#define CC 256
#define HW 1024
#define HEADS 8
#define HD 32
#define NG 8
#define GS 32

__device__ __align__(256) float g_h[BB * CC * HW];
__device__ __align__(256) float g_qkv[BB * 3 * CC * HW];
__device__ __align__(256) float g_ao[BB * CC * HW];

// ---------------------------------------------------------------------------
// Kernel 1: GroupNorm (validated)
// ---------------------------------------------------------------------------
__global__ __launch_bounds__(256) void gn_kernel(const float* __restrict__ x,
                                                 const float* __restrict__ sc,
                                                 const float* __restrict__ bi) {
    const int b = blockIdx.x / NG;
    const int g = blockIdx.x % NG;
    const int NE = GS * HW;
    const float* xp = x + ((size_t)b * CC + g * GS) * HW;
    float* hp = g_h + ((size_t)b * CC + g * GS) * HW;

    float s = 0.f, s2 = 0.f;
    const float4* x4 = (const float4*)xp;
    for (int i = threadIdx.x; i < NE / 4; i += 256) {
        float4 v = x4[i];
        s += v.x + v.y + v.z + v.w;
        s2 += v.x * v.x + v.y * v.y + v.z * v.z + v.w * v.w;
    }
    __shared__ float rs[256], rs2[256];
    rs[threadIdx.x] = s; rs2[threadIdx.x] = s2;
    __syncthreads();
    for (int o = 128; o > 0; o >>= 1) {
        if (threadIdx.x < o) {
            rs[threadIdx.x] += rs[threadIdx.x + o];
            rs2[threadIdx.x] += rs2[threadIdx.x + o];
        }
        __syncthreads();
    }
    const float mean = rs[0] / NE;
    const float var = rs2[0] / NE - mean * mean;
    const float rstd = rsqrtf(var + 1e-5f);

    float4* h4 = (float4*)hp;
    for (int i = threadIdx.x; i < NE / 4; i += 256) {
        const int c = g * GS + (i >> 8);
        const float a = sc[c] * rstd;
        const float d = bi[c] - mean * a;
        float4 v = x4[i];
        float4 o4;
        o4.x = v.x * a + d; o4.y = v.y * a + d;
        o4.z = v.z * a + d; o4.w = v.w * a + d;
        h4[i] = o4;
    }
}

// ---------------------------------------------------------------------------
// Kernel 2/4: WMMA TF32 GEMM with gmem prefetch of next k-chunk
// ---------------------------------------------------------------------------
template <int M_TOTAL, bool RESID>
__global__ __launch_bounds__(128) void gemm_wmma(const float* __restrict__ A,
                                                 const float* __restrict__ bias,
                                                 const float* __restrict__ Bmat,
                                                 const float* __restrict__ resid,
                                                 float* __restrict__ Cout) {
    const int bb = blockIdx.z;
    const int m0 = blockIdx.y * 64;
    const int n0 = blockIdx.x * 64;
    const float* Bp = Bmat + (size_t)bb * CC * HW;
    float* Cp = Cout + (size_t)bb * M_TOTAL * HW;
    const float* Rp = RESID ? (resid + (size_t)bb * M_TOTAL * HW) : nullptr;

    __shared__ __align__(128) float As[64][24];
    __shared__ __align__(128) float Bs[16][72];
    __shared__ __align__(128) float Cs[4][32][36];

    const int tid = threadIdx.x;
    const int w = tid >> 5;
    const int wm = (w >> 1) * 32;
    const int wn = (w & 1) * 32;

    wmma::fragment<wmma::accumulator, 16, 16, 8, float> fc[2][2];
#pragma unroll
    for (int i = 0; i < 2; i++)
#pragma unroll
        for (int j = 0; j < 2; j++) wmma::fill_fragment(fc[i][j], 0.0f);

    float4 av[2], bv[2];
#pragma unroll
    for (int t = 0; t < 2; t++) {
        const int id = tid + t * 128;
        av[t] = *(const float4*)(A + (size_t)(m0 + (id >> 2)) * CC + (id & 3) * 4);
        bv[t] = *(const float4*)(Bp + (size_t)(id >> 4) * HW + n0 + (id & 15) * 4);
    }

    for (int k0 = 0; k0 < CC; k0 += 16) {
        __syncthreads();
#pragma unroll
        for (int t = 0; t < 2; t++) {
            const int id = tid + t * 128;
            float* ap = &As[id >> 2][(id & 3) * 4];
            ap[0] = wmma::__float_to_tf32(av[t].x);
            ap[1] = wmma::__float_to_tf32(av[t].y);
            ap[2] = wmma::__float_to_tf32(av[t].z);
            ap[3] = wmma::__float_to_tf32(av[t].w);
            float* bp = &Bs[id >> 4][(id & 15) * 4];
            bp[0] = wmma::__float_to_tf32(bv[t].x);
            bp[1] = wmma::__float_to_tf32(bv[t].y);
            bp[2] = wmma::__float_to_tf32(bv[t].z);
            bp[3] = wmma::__float_to_tf32(bv[t].w);
        }
        __syncthreads();

        // prefetch next k-chunk while MMAs run
        if (k0 + 16 < CC) {
#pragma unroll
            for (int t = 0; t < 2; t++) {
                const int id = tid + t * 128;
                av[t] = *(const float4*)(A + (size_t)(m0 + (id >> 2)) * CC + k0 + 16 + (id & 3) * 4);
                bv[t] = *(const float4*)(Bp + (size_t)(k0 + 16 + (id >> 4)) * HW + n0 + (id & 15) * 4);
            }
        }

#pragma unroll
        for (int ks = 0; ks < 2; ks++) {
            wmma::fragment<wmma::matrix_a, 16, 16, 8, wmma::precision::tf32, wmma::row_major> fa[2];
            wmma::fragment<wmma::matrix_b, 16, 16, 8, wmma::precision::tf32, wmma::row_major> fb[2];
#pragma unroll
            for (int i = 0; i < 2; i++)
                wmma::load_matrix_sync(fa[i], &As[wm + i * 16][ks * 8], 24);
#pragma unroll
            for (int j = 0; j < 2; j++)
                wmma::load_matrix_sync(fb[j], &Bs[ks * 8][wn + j * 16], 72);
#pragma unroll
            for (int i = 0; i < 2; i++)
#pragma unroll
                for (int j = 0; j < 2; j++)
                    wmma::mma_sync(fc[i][j], fa[i], fb[j], fc[i][j]);
        }
    }

    __syncthreads();
#pragma unroll
    for (int i = 0; i < 2; i++)
#pragma unroll
        for (int j = 0; j < 2; j++)
            wmma::store_matrix_sync(&Cs[w][i * 16][j * 16], fc[i][j], 36, wmma::mem_row_major);
    __syncthreads();

#pragma unroll
    for (int t = 0; t < 8; t++) {
        const int id = tid + t * 128;
        const int r = id >> 4;
        const int c4 = (id & 15) * 4;
        const int wq = ((r >> 5) << 1) | (c4 >> 5);
        const float* cp = &Cs[wq][r & 31][c4 & 31];
        float4 v = *(const float4*)cp;
        const float bm = bias[m0 + r];
        v.x += bm; v.y += bm; v.z += bm; v.w += bm;
        if (RESID) {
            float4 rv = *(const float4*)(Rp + (size_t)(m0 + r) * HW + n0 + c4);
            v.x += rv.x; v.y += rv.y; v.z += rv.z; v.w += rv.w;
        }
        *(float4*)(Cp + (size_t)(m0 + r) * HW + n0 + c4) = v;
    }
}

// ---------------------------------------------------------------------------
// Kernel 3: WMMA TF32 flash attention — fully warp-local rows.
// Warp w owns q-rows [16w,16w+16) for S, softmax, O. Only K/V are shared
// => 2 block barriers per chunk. PV accumulates directly into Os via
// accumulator load/store.
// ---------------------------------------------------------------------------
__global__ __launch_bounds__(128) void attn_wmma() {
    const int qt = blockIdx.x & 15;
    const int bh = blockIdx.x >> 4;
    const int b = bh >> 3;
    const int h = bh & 7;
    const int n0q = qt * 64;

    const int tid = threadIdx.x;
    const int w = tid >> 5;
    const int lane = tid & 31;

    const float* base = g_qkv + (size_t)b * 3 * CC * HW;
    const float* qp = base + (size_t)(h * HD) * HW;
    const float* kp = base + (size_t)(CC + h * HD) * HW;
    const float* vp = base + (size_t)(2 * CC + h * HD) * HW;

    __shared__ __align__(128) float Ss[64][72];  // Q staging, then per-warp S/P
    __shared__ __align__(128) float Ks[32][72];  // K chunk [d][key] (shared)
    __shared__ __align__(128) float Vs[32][72];  // V chunk [d][key] (shared)
    __shared__ __align__(128) float Os[64][40];  // running output [q][d], warp-private rows

    const float scale = 0.17677669529663687f;

    // Stage Q transposed + zero O
    for (int i = tid; i < 64 * 32; i += 128) {
        const int d = i >> 6, q = i & 63;
        Ss[q][d] = wmma::__float_to_tf32(qp[(size_t)d * HW + n0q + q] * scale);
    }
    for (int i = tid; i < 64 * 40; i += 128) (&Os[0][0])[i] = 0.f;
    __syncthreads();

    wmma::fragment<wmma::matrix_a, 16, 16, 8, wmma::precision::tf32, wmma::row_major> fq[4];
#pragma unroll
    for (int ks = 0; ks < 4; ks++)
        wmma::load_matrix_sync(fq[ks], &Ss[w * 16][ks * 8], 72);
    // After this, warp w touches only its own Ss/Os rows — no block hazard.

    float m_run = -1e30f, l_run = 0.f;
    const int r = w * 16 + (lane >> 1);  // own softmax row (2 lanes/row)
    const int half = lane & 1;

    for (int m0 = 0; m0 < HW; m0 += 64) {
        __syncthreads();  // all warps done reading previous K/V
        for (int i = tid; i < 512; i += 128) {
            const int d = i >> 4, c4 = (i & 15) * 4;
            float4 kv = *(const float4*)(kp + (size_t)d * HW + m0 + c4);
            Ks[d][c4 + 0] = wmma::__float_to_tf32(kv.x);
            Ks[d][c4 + 1] = wmma::__float_to_tf32(kv.y);
            Ks[d][c4 + 2] = wmma::__float_to_tf32(kv.z);
            Ks[d][c4 + 3] = wmma::__float_to_tf32(kv.w);
            float4 vv = *(const float4*)(vp + (size_t)d * HW + m0 + c4);
            Vs[d][c4 + 0] = wmma::__float_to_tf32(vv.x);
            Vs[d][c4 + 1] = wmma::__float_to_tf32(vv.y);
            Vs[d][c4 + 2] = wmma::__float_to_tf32(vv.z);
            Vs[d][c4 + 3] = wmma::__float_to_tf32(vv.w);
        }
        __syncthreads();  // K/V ready

        // ---- S = Q K on own rows ----
        {
            wmma::fragment<wmma::accumulator, 16, 16, 8, float> sacc[4];
#pragma unroll
            for (int n = 0; n < 4; n++) wmma::fill_fragment(sacc[n], 0.0f);
#pragma unroll
            for (int ks = 0; ks < 4; ks++) {
#pragma unroll
                for (int n = 0; n < 4; n++) {
                    wmma::fragment<wmma::matrix_b, 16, 16, 8, wmma::precision::tf32, wmma::row_major> fb;
                    wmma::load_matrix_sync(fb, &Ks[ks * 8][n * 16], 72);
                    wmma::mma_sync(sacc[n], fq[ks], fb, sacc[n]);
                }
            }
#pragma unroll
            for (int n = 0; n < 4; n++)
                wmma::store_matrix_sync(&Ss[w * 16][n * 16], sacc[n], 72, wmma::mem_row_major);
        }
        __syncwarp();

        // ---- online softmax + O rescale (warp-local) ----
        {
            float* srow = &Ss[r][half * 32];
            float4 sv[8];
#pragma unroll
            for (int j = 0; j < 8; j++) sv[j] = ((float4*)srow)[j];
            float mx = -1e30f;
#pragma unroll
            for (int j = 0; j < 8; j++)
                mx = fmaxf(mx, fmaxf(fmaxf(sv[j].x, sv[j].y), fmaxf(sv[j].z, sv[j].w)));
            mx = fmaxf(mx, __shfl_xor_sync(0xffffffffu, mx, 1));
            const float nm = fmaxf(m_run, mx);
            const float alpha = __expf(m_run - nm);
            float psum = 0.f;
#pragma unroll
            for (int j = 0; j < 8; j++) {
                sv[j].x = __expf(sv[j].x - nm);
                sv[j].y = __expf(sv[j].y - nm);
                sv[j].z = __expf(sv[j].z - nm);
                sv[j].w = __expf(sv[j].w - nm);
                psum += sv[j].x + sv[j].y + sv[j].z + sv[j].w;
                float4 o4;
                o4.x = wmma::__float_to_tf32(sv[j].x);
                o4.y = wmma::__float_to_tf32(sv[j].y);
                o4.z = wmma::__float_to_tf32(sv[j].z);
                o4.w = wmma::__float_to_tf32(sv[j].w);
                ((float4*)srow)[j] = o4;
            }
            psum += __shfl_xor_sync(0xffffffffu, psum, 1);
            l_run = l_run * alpha + psum;
            m_run = nm;
            float4* orow = (float4*)&Os[r][half * 16];
#pragma unroll
            for (int j = 0; j < 4; j++) {
                float4 v = orow[j];
                v.x *= alpha; v.y *= alpha; v.z *= alpha; v.w *= alpha;
                orow[j] = v;
            }
        }
        __syncwarp();

        // ---- Os += P V (accumulate directly into Os fragments) ----
        {
            wmma::fragment<wmma::matrix_a, 16, 16, 8, wmma::precision::tf32, wmma::row_major> fp[8];
#pragma unroll
            for (int k = 0; k < 8; k++)
                wmma::load_matrix_sync(fp[k], &Ss[w * 16][k * 8], 72);
            wmma::fragment<wmma::accumulator, 16, 16, 8, float> oacc[2];
#pragma unroll
            for (int n = 0; n < 2; n++)
                wmma::load_matrix_sync(oacc[n], &Os[w * 16][n * 16], 40, wmma::mem_row_major);
#pragma unroll
            for (int k = 0; k < 8; k++) {
#pragma unroll
                for (int n = 0; n < 2; n++) {
                    wmma::fragment<wmma::matrix_b, 16, 16, 8, wmma::precision::tf32, wmma::col_major> fv;
                    wmma::load_matrix_sync(fv, &Vs[0][0] + n * 16 * 72 + k * 8, 72);
                    wmma::mma_sync(oacc[n], fp[k], fv, oacc[n]);
                }
            }
#pragma unroll
            for (int n = 0; n < 2; n++)
                wmma::store_matrix_sync(&Os[w * 16][n * 16], oacc[n], 40, wmma::mem_row_major);
        }
        __syncwarp();
    }

    // ---- finalize (warp-local rows) ----
    const float inv = 1.f / l_run;
    float* aob = g_ao + ((size_t)b * CC + h * HD) * HW;
#pragma unroll
    for (int j = 0; j < 16; j++) {
        const int d = half * 16 + j;
        aob[(size_t)d * HW + n0q + r] = Os[r][d] * inv;
    }
}

// ---------------------------------------------------------------------------
extern "C" void kernel_launch(void* const* d_in, const int* in_sizes, int n_in,
                              void* d_out, int out_size) {
    const float* x = (const float*)d_in[0];
    const float* gn_scale = (const float*)d_in[1];
    const float* gn_bias = (const float*)d_in[2];
    const float* w_qkv = (const float*)d_in[3];
    const float* b_qkv = (const float*)d_in[4];
    const float* w_out = (const float*)d_in[5];
    const float* b_out = (const float*)d_in[6];
    float* out = (float*)d_out;

    float* hbuf; cudaGetSymbolAddress((void**)&hbuf, g_h);
    float* qkv;  cudaGetSymbolAddress((void**)&qkv, g_qkv);
    float* ao;   cudaGetSymbolAddress((void**)&ao, g_ao);

    gn_kernel<<<BB * NG, 256>>>(x, gn_scale, gn_bias);

    {
        dim3 grid(HW / 64, (3 * CC) / 64, BB);
        gemm_wmma<3 * CC, false><<<grid, 128>>>(w_qkv, b_qkv, hbuf, nullptr, qkv);
    }

    attn_wmma<<<BB * HEADS * 16, 128>>>();

    {
        dim3 grid(HW / 64, CC / 64, BB);
        gemm_wmma<CC, true><<<grid, 128>>>(w_out, b_out, ao, x, out);
    }
}

// round 7
// speedup vs baseline: 2.3023x; 1.1919x over previous
#include <cuda_runtime.h>
#include <cuda_bf16.h>
#include <mma.h>

using namespace nvcuda;

#define BB 8
#define CC 256
#define HW 1024
#define HEADS 8
#define HD 32
#define NG 8
#define GS 32

__device__ __align__(256) float g_h[BB * CC * HW];
__device__ __align__(256) float g_qkv[BB * 3 * CC * HW];
__device__ __align__(256) float g_ao[BB * CC * HW];

// ---------------------------------------------------------------------------
__device__ __forceinline__ void mma_bf16(float c[4], unsigned a0, unsigned a1,
                                         unsigned a2, unsigned a3,
                                         unsigned b0, unsigned b1) {
    asm volatile(
        "mma.sync.aligned.m16n8k16.row.col.f32.bf16.bf16.f32 "
        "{%0,%1,%2,%3},{%4,%5,%6,%7},{%8,%9},{%0,%1,%2,%3};"
        : "+f"(c[0]), "+f"(c[1]), "+f"(c[2]), "+f"(c[3])
        : "r"(a0), "r"(a1), "r"(a2), "r"(a3), "r"(b0), "r"(b1));
}

__device__ __forceinline__ float ex2(float x) {
    float r;
    asm("ex2.approx.f32 %0, %1;" : "=f"(r) : "f"(x));
    return r;
}

__device__ __forceinline__ unsigned pack_bf16(float lo, float hi) {
    __nv_bfloat162 t = __floats2bfloat162_rn(lo, hi);
    return *(unsigned*)&t;
}

// ---------------------------------------------------------------------------
// Kernel 1: GroupNorm (validated)
// ---------------------------------------------------------------------------
__global__ __launch_bounds__(256) void gn_kernel(const float* __restrict__ x,
                                                 const float* __restrict__ sc,
                                                 const float* __restrict__ bi) {
    const int b = blockIdx.x / NG;
    const int g = blockIdx.x % NG;
    const int NE = GS * HW;
    const float* xp = x + ((size_t)b * CC + g * GS) * HW;
    float* hp = g_h + ((size_t)b * CC + g * GS) * HW;

    float s = 0.f, s2 = 0.f;
    const float4* x4 = (const float4*)xp;
    for (int i = threadIdx.x; i < NE / 4; i += 256) {
        float4 v = x4[i];
        s += v.x + v.y + v.z + v.w;
        s2 += v.x * v.x + v.y * v.y + v.z * v.z + v.w * v.w;
    }
    __shared__ float rs[256], rs2[256];
    rs[threadIdx.x] = s; rs2[threadIdx.x] = s2;
    __syncthreads();
    for (int o = 128; o > 0; o >>= 1) {
        if (threadIdx.x < o) {
            rs[threadIdx.x] += rs[threadIdx.x + o];
            rs2[threadIdx.x] += rs2[threadIdx.x + o];
        }
        __syncthreads();
    }
    const float mean = rs[0] / NE;
    const float var = rs2[0] / NE - mean * mean;
    const float rstd = rsqrtf(var + 1e-5f);

    float4* h4 = (float4*)hp;
    for (int i = threadIdx.x; i < NE / 4; i += 256) {
        const int c = g * GS + (i >> 8);
        const float a = sc[c] * rstd;
        const float d = bi[c] - mean * a;
        float4 v = x4[i];
        float4 o4;
        o4.x = v.x * a + d; o4.y = v.y * a + d;
        o4.z = v.z * a + d; o4.w = v.w * a + d;
        h4[i] = o4;
    }
}

// ---------------------------------------------------------------------------
// Kernel 2/4: WMMA TF32 GEMM (validated, 285us version)
// ---------------------------------------------------------------------------
template <int M_TOTAL, bool RESID>
__global__ __launch_bounds__(128) void gemm_wmma(const float* __restrict__ A,
                                                 const float* __restrict__ bias,
                                                 const float* __restrict__ Bmat,
                                                 const float* __restrict__ resid,
                                                 float* __restrict__ Cout) {
    const int bb = blockIdx.z;
    const int m0 = blockIdx.y * 64;
    const int n0 = blockIdx.x * 64;
    const float* Bp = Bmat + (size_t)bb * CC * HW;
    float* Cp = Cout + (size_t)bb * M_TOTAL * HW;
    const float* Rp = RESID ? (resid + (size_t)bb * M_TOTAL * HW) : nullptr;

    __shared__ __align__(128) float As[64][24];
    __shared__ __align__(128) float Bs[16][72];
    __shared__ __align__(128) float Cs[4][32][36];

    const int tid = threadIdx.x;
    const int w = tid >> 5;
    const int wm = (w >> 1) * 32;
    const int wn = (w & 1) * 32;

    wmma::fragment<wmma::accumulator, 16, 16, 8, float> fc[2][2];
#pragma unroll
    for (int i = 0; i < 2; i++)
#pragma unroll
        for (int j = 0; j < 2; j++) wmma::fill_fragment(fc[i][j], 0.0f);

    float4 av[2], bv[2];
#pragma unroll
    for (int t = 0; t < 2; t++) {
        const int id = tid + t * 128;
        av[t] = *(const float4*)(A + (size_t)(m0 + (id >> 2)) * CC + (id & 3) * 4);
        bv[t] = *(const float4*)(Bp + (size_t)(id >> 4) * HW + n0 + (id & 15) * 4);
    }

    for (int k0 = 0; k0 < CC; k0 += 16) {
        __syncthreads();
#pragma unroll
        for (int t = 0; t < 2; t++) {
            const int id = tid + t * 128;
            float* ap = &As[id >> 2][(id & 3) * 4];
            ap[0] = wmma::__float_to_tf32(av[t].x);
            ap[1] = wmma::__float_to_tf32(av[t].y);
            ap[2] = wmma::__float_to_tf32(av[t].z);
            ap[3] = wmma::__float_to_tf32(av[t].w);
            float* bp = &Bs[id >> 4][(id & 15) * 4];
            bp[0] = wmma::__float_to_tf32(bv[t].x);
            bp[1] = wmma::__float_to_tf32(bv[t].y);
            bp[2] = wmma::__float_to_tf32(bv[t].z);
            bp[3] = wmma::__float_to_tf32(bv[t].w);
        }
        __syncthreads();

        if (k0 + 16 < CC) {
#pragma unroll
            for (int t = 0; t < 2; t++) {
                const int id = tid + t * 128;
                av[t] = *(const float4*)(A + (size_t)(m0 + (id >> 2)) * CC + k0 + 16 + (id & 3) * 4);
                bv[t] = *(const float4*)(Bp + (size_t)(k0 + 16 + (id >> 4)) * HW + n0 + (id & 15) * 4);
            }
        }

#pragma unroll
        for (int ks = 0; ks < 2; ks++) {
            wmma::fragment<wmma::matrix_a, 16, 16, 8, wmma::precision::tf32, wmma::row_major> fa[2];
            wmma::fragment<wmma::matrix_b, 16, 16, 8, wmma::precision::tf32, wmma::row_major> fb[2];
#pragma unroll
            for (int i = 0; i < 2; i++)
                wmma::load_matrix_sync(fa[i], &As[wm + i * 16][ks * 8], 24);
#pragma unroll
            for (int j = 0; j < 2; j++)
                wmma::load_matrix_sync(fb[j], &Bs[ks * 8][wn + j * 16], 72);
#pragma unroll
            for (int i = 0; i < 2; i++)
#pragma unroll
                for (int j = 0; j < 2; j++)
                    wmma::mma_sync(fc[i][j], fa[i], fb[j], fc[i][j]);
        }
    }

    __syncthreads();
#pragma unroll
    for (int i = 0; i < 2; i++)
#pragma unroll
        for (int j = 0; j < 2; j++)
            wmma::store_matrix_sync(&Cs[w][i * 16][j * 16], fc[i][j], 36, wmma::mem_row_major);
    __syncthreads();

#pragma unroll
    for (int t = 0; t < 8; t++) {
        const int id = tid + t * 128;
        const int r = id >> 4;
        const int c4 = (id & 15) * 4;
        const int wq = ((r >> 5) << 1) | (c4 >> 5);
        const float* cp = &Cs[wq][r & 31][c4 & 31];
        float4 v = *(const float4*)cp;
        const float bm = bias[m0 + r];
        v.x += bm; v.y += bm; v.z += bm; v.w += bm;
        if (RESID) {
            float4 rv = *(const float4*)(Rp + (size_t)(m0 + r) * HW + n0 + c4);
            v.x += rv.x; v.y += rv.y; v.z += rv.z; v.w += rv.w;
        }
        *(float4*)(Cp + (size_t)(m0 + r) * HW + n0 + c4) = v;
    }
}

// ---------------------------------------------------------------------------
// Kernel 3: bf16 flash attention, FA2-style register-resident.
// Block = (b, h, 64-q tile), 128 threads / 4 warps; warp w owns q rows
// [16w,16w+16). S acc (fp32) in regs -> softmax in regs -> P repacked as
// bf16x2 A-frags in regs -> O acc (fp32) in regs across all chunks.
// Smem: Q staging, K^T chunk [key][d], V chunk [d][key], final O transpose.
// mma.sync.m16n8k16 fragment layouts per PTX ISA:
//   C: c0,c1 = (row lane>>2, cols 2(lane&3),+1); c2,c3 = row+8.
//   A: a0=(r, k 2l4,+1) a1=(r+8, same) a2=(r, k+8) a3=(r+8, k+8) as bf16x2.
//   B: b0=(k 2l4,+1; n lane>>2) b1=(k 2l4+8,+9; same n) as bf16x2.
// ---------------------------------------------------------------------------
__global__ __launch_bounds__(128) void attn_bf16() {
    const int qt = blockIdx.x & 15;
    const int bh = blockIdx.x >> 4;
    const int b = bh >> 3;
    const int h = bh & 7;
    const int n0q = qt * 64;

    const int tid = threadIdx.x;
    const int lane = tid & 31;
    const int w = tid >> 5;
    const int lq = lane >> 2;
    const int l4 = lane & 3;

    const float* base = g_qkv + (size_t)b * 3 * CC * HW;
    const float* qp = base + (size_t)(h * HD) * HW;
    const float* kp = base + (size_t)(CC + h * HD) * HW;
    const float* vp = base + (size_t)(2 * CC + h * HD) * HW;

    __shared__ __align__(128) __nv_bfloat16 Qs[64][42];  // [q][d]
    __shared__ __align__(128) __nv_bfloat16 Ks[64][42];  // [key][d] (transposed)
    __shared__ __align__(128) __nv_bfloat16 Vs[32][72];  // [d][key] (direct)
    __shared__ __align__(128) float Of[32][68];          // [d][q] final transpose

    // fold softmax scale and log2(e) into Q so we can use ex2 directly
    const float qscale = 0.17677669529663687f * 1.4426950408889634f;

    // ---- stage Q transposed: Qs[q][d] ----
#pragma unroll
    for (int t = 0; t < 4; t++) {
        const int i = tid + t * 128;
        const int d = i >> 4, qb = (i & 15) * 4;
        float4 v = *(const float4*)(qp + (size_t)d * HW + n0q + qb);
        Qs[qb + 0][d] = __float2bfloat16_rn(v.x * qscale);
        Qs[qb + 1][d] = __float2bfloat16_rn(v.y * qscale);
        Qs[qb + 2][d] = __float2bfloat16_rn(v.z * qscale);
        Qs[qb + 3][d] = __float2bfloat16_rn(v.w * qscale);
    }
    __syncthreads();

    // ---- Q A-fragments in registers for whole kernel (2 k16-tiles over d) ----
    unsigned aQ[2][4];
    const int q0 = w * 16 + lq;
#pragma unroll
    for (int t = 0; t < 2; t++) {
        aQ[t][0] = *(const unsigned*)&Qs[q0][t * 16 + 2 * l4];
        aQ[t][1] = *(const unsigned*)&Qs[q0 + 8][t * 16 + 2 * l4];
        aQ[t][2] = *(const unsigned*)&Qs[q0][t * 16 + 2 * l4 + 8];
        aQ[t][3] = *(const unsigned*)&Qs[q0 + 8][t * 16 + 2 * l4 + 8];
    }

    float oacc[4][4];
#pragma unroll
    for (int j = 0; j < 4; j++)
#pragma unroll
        for (int r = 0; r < 4; r++) oacc[j][r] = 0.f;
    float m0run = -1e30f, m1run = -1e30f;
    float l0run = 0.f, l1run = 0.f;

    for (int m0 = 0; m0 < HW; m0 += 64) {
        __syncthreads();  // previous chunk's fragment reads complete
        // ---- load K (transposed into [key][d]) and V (direct [d][key]) ----
#pragma unroll
        for (int t = 0; t < 4; t++) {
            const int i = tid + t * 128;
            const int d = i >> 4, kb = (i & 15) * 4;
            float4 kv = *(const float4*)(kp + (size_t)d * HW + m0 + kb);
            Ks[kb + 0][d] = __float2bfloat16_rn(kv.x);
            Ks[kb + 1][d] = __float2bfloat16_rn(kv.y);
            Ks[kb + 2][d] = __float2bfloat16_rn(kv.z);
            Ks[kb + 3][d] = __float2bfloat16_rn(kv.w);
            float4 vv = *(const float4*)(vp + (size_t)d * HW + m0 + kb);
            *(unsigned*)&Vs[d][kb] = pack_bf16(vv.x, vv.y);
            *(unsigned*)&Vs[d][kb + 2] = pack_bf16(vv.z, vv.w);
        }
        __syncthreads();  // K/V ready

        // ---- S = Q K^T : 16 q-rows x 64 keys, fp32 acc in regs ----
        float sc[8][4];
#pragma unroll
        for (int j = 0; j < 8; j++)
#pragma unroll
            for (int r = 0; r < 4; r++) sc[j][r] = 0.f;
#pragma unroll
        for (int t = 0; t < 2; t++) {
#pragma unroll
            for (int j = 0; j < 8; j++) {
                unsigned b0 = *(const unsigned*)&Ks[j * 8 + lq][t * 16 + 2 * l4];
                unsigned b1 = *(const unsigned*)&Ks[j * 8 + lq][t * 16 + 2 * l4 + 8];
                mma_bf16(sc[j], aQ[t][0], aQ[t][1], aQ[t][2], aQ[t][3], b0, b1);
            }
        }

        // ---- online softmax entirely in registers (rows q0 and q0+8) ----
        float mx0 = -1e30f, mx1 = -1e30f;
#pragma unroll
        for (int j = 0; j < 8; j++) {
            mx0 = fmaxf(mx0, fmaxf(sc[j][0], sc[j][1]));
            mx1 = fmaxf(mx1, fmaxf(sc[j][2], sc[j][3]));
        }
        mx0 = fmaxf(mx0, __shfl_xor_sync(0xffffffffu, mx0, 1));
        mx0 = fmaxf(mx0, __shfl_xor_sync(0xffffffffu, mx0, 2));
        mx1 = fmaxf(mx1, __shfl_xor_sync(0xffffffffu, mx1, 1));
        mx1 = fmaxf(mx1, __shfl_xor_sync(0xffffffffu, mx1, 2));

        const float nm0 = fmaxf(m0run, mx0);
        const float nm1 = fmaxf(m1run, mx1);
        const float al0 = ex2(m0run - nm0);
        const float al1 = ex2(m1run - nm1);
        m0run = nm0; m1run = nm1;

        unsigned pa01[8], pa23[8];
        float ls0 = 0.f, ls1 = 0.f;
#pragma unroll
        for (int j = 0; j < 8; j++) {
            const float p0 = ex2(sc[j][0] - nm0);
            const float p1 = ex2(sc[j][1] - nm0);
            const float p2 = ex2(sc[j][2] - nm1);
            const float p3 = ex2(sc[j][3] - nm1);
            ls0 += p0 + p1;
            ls1 += p2 + p3;
            pa01[j] = pack_bf16(p0, p1);  // (row q0,   keys 2l4,2l4+1 of n-tile j)
            pa23[j] = pack_bf16(p2, p3);  // (row q0+8, same keys)
        }
        ls0 += __shfl_xor_sync(0xffffffffu, ls0, 1);
        ls0 += __shfl_xor_sync(0xffffffffu, ls0, 2);
        ls1 += __shfl_xor_sync(0xffffffffu, ls1, 1);
        ls1 += __shfl_xor_sync(0xffffffffu, ls1, 2);
        l0run = l0run * al0 + ls0;
        l1run = l1run * al1 + ls1;

        // rescale O (rows match C layout: c0,c1 row q0; c2,c3 row q0+8)
#pragma unroll
        for (int j = 0; j < 4; j++) {
            oacc[j][0] *= al0; oacc[j][1] *= al0;
            oacc[j][2] *= al1; oacc[j][3] *= al1;
        }

        // ---- O += P V : P A-frags straight from registers ----
#pragma unroll
        for (int t = 0; t < 4; t++) {  // k16-tiles over keys
            const unsigned a0 = pa01[2 * t];
            const unsigned a1 = pa23[2 * t];
            const unsigned a2 = pa01[2 * t + 1];
            const unsigned a3 = pa23[2 * t + 1];
#pragma unroll
            for (int j = 0; j < 4; j++) {  // n8-tiles over d
                unsigned b0 = *(const unsigned*)&Vs[j * 8 + lq][t * 16 + 2 * l4];
                unsigned b1 = *(const unsigned*)&Vs[j * 8 + lq][t * 16 + 2 * l4 + 8];
                mma_bf16(oacc[j], a0, a1, a2, a3, b0, b1);
            }
        }
    }

    // ---- finalize: normalize, transpose via smem, coalesced store ----
    __syncthreads();
    const float inv0 = 1.f / l0run;
    const float inv1 = 1.f / l1run;
#pragma unroll
    for (int j = 0; j < 4; j++) {
        const int d = j * 8 + 2 * l4;
        Of[d][q0] = oacc[j][0] * inv0;
        Of[d + 1][q0] = oacc[j][1] * inv0;
        Of[d][q0 + 8] = oacc[j][2] * inv1;
        Of[d + 1][q0 + 8] = oacc[j][3] * inv1;
    }
    __syncthreads();

    float* aob = g_ao + ((size_t)b * CC + h * HD) * HW;
#pragma unroll
    for (int t = 0; t < 4; t++) {
        const int i = tid + t * 128;
        const int d = i >> 4, q4 = (i & 15) * 4;
        float4 v = *(const float4*)&Of[d][q4];
        *(float4*)(aob + (size_t)d * HW + n0q + q4) = v;
    }
}

// ---------------------------------------------------------------------------
extern "C" void kernel_launch(void* const* d_in, const int* in_sizes, int n_in,
                              void* d_out, int out_size) {
    const float* x = (const float*)d_in[0];
    const float* gn_scale = (const float*)d_in[1];
    const float* gn_bias = (const float*)d_in[2];
    const float* w_qkv = (const float*)d_in[3];
    const float* b_qkv = (const float*)d_in[4];
    const float* w_out = (const float*)d_in[5];
    const float* b_out = (const float*)d_in[6];
    float* out = (float*)d_out;

    float* hbuf; cudaGetSymbolAddress((void**)&hbuf, g_h);
    float* qkv;  cudaGetSymbolAddress((void**)&qkv, g_qkv);
    float* ao;   cudaGetSymbolAddress((void**)&ao, g_ao);

    gn_kernel<<<BB * NG, 256>>>(x, gn_scale, gn_bias);

    {
        dim3 grid(HW / 64, (3 * CC) / 64, BB);
        gemm_wmma<3 * CC, false><<<grid, 128>>>(w_qkv, b_qkv, hbuf, nullptr, qkv);
    }

    attn_bf16<<<BB * HEADS * 16, 128>>>();

    {
        dim3 grid(HW / 64, CC / 64, BB);
        gemm_wmma<CC, true><<<grid, 128>>>(w_out, b_out, ao, x, out);
    }
}

// round 8
// speedup vs baseline: 3.5780x; 1.5541x over previous
#include <cuda_runtime.h>
#include <cuda_bf16.h>
#include <mma.h>

using namespace nvcuda;

#define BB 8
#define CC 256
#define HW 1024
#define HEADS 8
#define HD 32
#define NG 8
#define GS 32

__device__ __align__(256) float g_h[BB * CC * HW];
__device__ __align__(256) float g_qkv[BB * 3 * CC * HW];
__device__ __align__(256) float g_ao[BB * CC * HW];

// ---------------------------------------------------------------------------
__device__ __forceinline__ void mma_bf16(float c[4], unsigned a0, unsigned a1,
                                         unsigned a2, unsigned a3,
                                         unsigned b0, unsigned b1) {
    asm volatile(
        "mma.sync.aligned.m16n8k16.row.col.f32.bf16.bf16.f32 "
        "{%0,%1,%2,%3},{%4,%5,%6,%7},{%8,%9},{%0,%1,%2,%3};"
        : "+f"(c[0]), "+f"(c[1]), "+f"(c[2]), "+f"(c[3])
        : "r"(a0), "r"(a1), "r"(a2), "r"(a3), "r"(b0), "r"(b1));
}

__device__ __forceinline__ float ex2(float x) {
    float r;
    asm("ex2.approx.f32 %0, %1;" : "=f"(r) : "f"(x));
    return r;
}

__device__ __forceinline__ unsigned pack_bf16(float lo, float hi) {
    __nv_bfloat162 t = __floats2bfloat162_rn(lo, hi);
    return *(unsigned*)&t;
}

__device__ __forceinline__ void cp16(float* smem, const float* gmem) {
    unsigned s = (unsigned)__cvta_generic_to_shared(smem);
    asm volatile("cp.async.ca.shared.global [%0], [%1], 16;" :: "r"(s), "l"(gmem));
}

// ---------------------------------------------------------------------------
// Kernel 1: GroupNorm (validated)
// ---------------------------------------------------------------------------
__global__ __launch_bounds__(256) void gn_kernel(const float* __restrict__ x,
                                                 const float* __restrict__ sc,
                                                 const float* __restrict__ bi) {
    const int b = blockIdx.x / NG;
    const int g = blockIdx.x % NG;
    const int NE = GS * HW;
    const float* xp = x + ((size_t)b * CC + g * GS) * HW;
    float* hp = g_h + ((size_t)b * CC + g * GS) * HW;

    float s = 0.f, s2 = 0.f;
    const float4* x4 = (const float4*)xp;
    for (int i = threadIdx.x; i < NE / 4; i += 256) {
        float4 v = x4[i];
        s += v.x + v.y + v.z + v.w;
        s2 += v.x * v.x + v.y * v.y + v.z * v.z + v.w * v.w;
    }
    __shared__ float rs[256], rs2[256];
    rs[threadIdx.x] = s; rs2[threadIdx.x] = s2;
    __syncthreads();
    for (int o = 128; o > 0; o >>= 1) {
        if (threadIdx.x < o) {
            rs[threadIdx.x] += rs[threadIdx.x + o];
            rs2[threadIdx.x] += rs2[threadIdx.x + o];
        }
        __syncthreads();
    }
    const float mean = rs[0] / NE;
    const float var = rs2[0] / NE - mean * mean;
    const float rstd = rsqrtf(var + 1e-5f);

    float4* h4 = (float4*)hp;
    for (int i = threadIdx.x; i < NE / 4; i += 256) {
        const int c = g * GS + (i >> 8);
        const float a = sc[c] * rstd;
        const float d = bi[c] - mean * a;
        float4 v = x4[i];
        float4 o4;
        o4.x = v.x * a + d; o4.y = v.y * a + d;
        o4.z = v.z * a + d; o4.w = v.w * a + d;
        h4[i] = o4;
    }
}

// ---------------------------------------------------------------------------
// Kernel 2/4: cp.async double-buffered TF32 GEMM.
// 128x128 block tile, 256 threads / 8 warps (warp = 32x64).
// Raw fp32 staged via cp.async; HMMA tf32 truncates mantissa in HW (no cvt).
// Smem union: staging (2 stages A[128][24] + B[16][136]) reused as the
// epilogue buffer (4 warps x 32x68) in 2 passes.
// ---------------------------------------------------------------------------
#define AS_PITCH 24
#define BS_PITCH 136
#define AS_STG 3072            // 128*24
#define BS_BASE 6144           // 2*AS_STG
#define BS_STG 2176            // 16*136
#define EP_PITCH 68
#define EP_STG 2176            // 32*68
#define SMF 10496              // total floats (41984 B)

template <int M_TOTAL, bool RESID>
__global__ __launch_bounds__(256, 2) void gemm_tc2(const float* __restrict__ A,
                                                   const float* __restrict__ bias,
                                                   const float* __restrict__ Bmat,
                                                   const float* __restrict__ resid,
                                                   float* __restrict__ Cout) {
    const int bb = blockIdx.z;
    const int m0 = blockIdx.y * 128;
    const int n0 = blockIdx.x * 128;
    const float* Bp = Bmat + (size_t)bb * CC * HW;
    float* Cp = Cout + (size_t)bb * M_TOTAL * HW;
    const float* Rp = RESID ? (resid + (size_t)bb * M_TOTAL * HW) : nullptr;

    __shared__ __align__(128) float sm[SMF];

    const int tid = threadIdx.x;
    const int w = tid >> 5;
    const int wm = (w >> 1) * 32;
    const int wn = (w & 1) * 64;

    wmma::fragment<wmma::accumulator, 16, 16, 8, float> fc[2][4];
#pragma unroll
    for (int i = 0; i < 2; i++)
#pragma unroll
        for (int j = 0; j < 4; j++) wmma::fill_fragment(fc[i][j], 0.0f);

#define COPY_STAGE(st, k0)                                                        \
    do {                                                                          \
        _Pragma("unroll")                                                         \
        for (int t = 0; t < 2; t++) {                                             \
            const int id = tid + t * 256;                                         \
            const int r_ = id >> 2, kc_ = (id & 3) * 4;                           \
            cp16(&sm[(st) * AS_STG + r_ * AS_PITCH + kc_],                        \
                 A + (size_t)(m0 + r_) * CC + (k0) + kc_);                        \
        }                                                                         \
        _Pragma("unroll")                                                         \
        for (int t = 0; t < 2; t++) {                                             \
            const int id = tid + t * 256;                                         \
            const int k_ = id >> 5, nc_ = (id & 31) * 4;                          \
            cp16(&sm[BS_BASE + (st) * BS_STG + k_ * BS_PITCH + nc_],              \
                 Bp + (size_t)((k0) + k_) * HW + n0 + nc_);                       \
        }                                                                         \
        asm volatile("cp.async.commit_group;" ::: "memory");                      \
    } while (0)

    COPY_STAGE(0, 0);

    for (int it = 0; it < 16; it++) {
        const int st = it & 1;
        if (it < 15) {
            COPY_STAGE(st ^ 1, (it + 1) * 16);
            asm volatile("cp.async.wait_group 1;" ::: "memory");
        } else {
            asm volatile("cp.async.wait_group 0;" ::: "memory");
        }
        __syncthreads();

#pragma unroll
        for (int ks = 0; ks < 2; ks++) {
            wmma::fragment<wmma::matrix_a, 16, 16, 8, wmma::precision::tf32, wmma::row_major> fa[2];
            wmma::fragment<wmma::matrix_b, 16, 16, 8, wmma::precision::tf32, wmma::row_major> fb[4];
#pragma unroll
            for (int i = 0; i < 2; i++)
                wmma::load_matrix_sync(fa[i], &sm[st * AS_STG + (wm + i * 16) * AS_PITCH + ks * 8], AS_PITCH);
#pragma unroll
            for (int j = 0; j < 4; j++)
                wmma::load_matrix_sync(fb[j], &sm[BS_BASE + st * BS_STG + (ks * 8) * BS_PITCH + wn + j * 16], BS_PITCH);
#pragma unroll
            for (int i = 0; i < 2; i++)
#pragma unroll
                for (int j = 0; j < 4; j++)
                    wmma::mma_sync(fc[i][j], fa[i], fb[j], fc[i][j]);
        }
        __syncthreads();
    }

    // ---- epilogue: 2 passes of 4 warps through the staging smem ----
#pragma unroll
    for (int p = 0; p < 2; p++) {
        if ((w >> 2) == p) {
            const int wl = w & 3;
#pragma unroll
            for (int i = 0; i < 2; i++)
#pragma unroll
                for (int j = 0; j < 4; j++)
                    wmma::store_matrix_sync(&sm[wl * EP_STG + (i * 16) * EP_PITCH + j * 16],
                                            fc[i][j], EP_PITCH, wmma::mem_row_major);
        }
        __syncthreads();
#pragma unroll
        for (int t = 0; t < 8; t++) {
            const int id = tid + t * 256;
            const int r = id >> 5;            // 0..63
            const int c4 = (id & 31) * 4;     // 0..124
            const int m = m0 + p * 64 + r;
            const int wq = ((r >> 5) << 1) | (c4 >> 6);
            const float* cp = &sm[wq * EP_STG + (r & 31) * EP_PITCH + (c4 & 63)];
            float4 v = *(const float4*)cp;
            const float bm = bias[m];
            v.x += bm; v.y += bm; v.z += bm; v.w += bm;
            if (RESID) {
                float4 rv = *(const float4*)(Rp + (size_t)m * HW + n0 + c4);
                v.x += rv.x; v.y += rv.y; v.z += rv.z; v.w += rv.w;
            }
            *(float4*)(Cp + (size_t)m * HW + n0 + c4) = v;
        }
        __syncthreads();
    }
#undef COPY_STAGE
}

// ---------------------------------------------------------------------------
// Kernel 3: bf16 flash attention, FA2-style register-resident (validated)
// ---------------------------------------------------------------------------
__global__ __launch_bounds__(128) void attn_bf16() {
    const int qt = blockIdx.x & 15;
    const int bh = blockIdx.x >> 4;
    const int b = bh >> 3;
    const int h = bh & 7;
    const int n0q = qt * 64;

    const int tid = threadIdx.x;
    const int lane = tid & 31;
    const int w = tid >> 5;
    const int lq = lane >> 2;
    const int l4 = lane & 3;

    const float* base = g_qkv + (size_t)b * 3 * CC * HW;
    const float* qp = base + (size_t)(h * HD) * HW;
    const float* kp = base + (size_t)(CC + h * HD) * HW;
    const float* vp = base + (size_t)(2 * CC + h * HD) * HW;

    __shared__ __align__(128) __nv_bfloat16 Qs[64][42];
    __shared__ __align__(128) __nv_bfloat16 Ks[64][42];
    __shared__ __align__(128) __nv_bfloat16 Vs[32][72];
    __shared__ __align__(128) float Of[32][68];

    const float qscale = 0.17677669529663687f * 1.4426950408889634f;

#pragma unroll
    for (int t = 0; t < 4; t++) {
        const int i = tid + t * 128;
        const int d = i >> 4, qb = (i & 15) * 4;
        float4 v = *(const float4*)(qp + (size_t)d * HW + n0q + qb);
        Qs[qb + 0][d] = __float2bfloat16_rn(v.x * qscale);
        Qs[qb + 1][d] = __float2bfloat16_rn(v.y * qscale);
        Qs[qb + 2][d] = __float2bfloat16_rn(v.z * qscale);
        Qs[qb + 3][d] = __float2bfloat16_rn(v.w * qscale);
    }
    __syncthreads();

    unsigned aQ[2][4];
    const int q0 = w * 16 + lq;
#pragma unroll
    for (int t = 0; t < 2; t++) {
        aQ[t][0] = *(const unsigned*)&Qs[q0][t * 16 + 2 * l4];
        aQ[t][1] = *(const unsigned*)&Qs[q0 + 8][t * 16 + 2 * l4];
        aQ[t][2] = *(const unsigned*)&Qs[q0][t * 16 + 2 * l4 + 8];
        aQ[t][3] = *(const unsigned*)&Qs[q0 + 8][t * 16 + 2 * l4 + 8];
    }

    float oacc[4][4];
#pragma unroll
    for (int j = 0; j < 4; j++)
#pragma unroll
        for (int r = 0; r < 4; r++) oacc[j][r] = 0.f;
    float m0run = -1e30f, m1run = -1e30f;
    float l0run = 0.f, l1run = 0.f;

    for (int m0 = 0; m0 < HW; m0 += 64) {
        __syncthreads();
#pragma unroll
        for (int t = 0; t < 4; t++) {
            const int i = tid + t * 128;
            const int d = i >> 4, kb = (i & 15) * 4;
            float4 kv = *(const float4*)(kp + (size_t)d * HW + m0 + kb);
            Ks[kb + 0][d] = __float2bfloat16_rn(kv.x);
            Ks[kb + 1][d] = __float2bfloat16_rn(kv.y);
            Ks[kb + 2][d] = __float2bfloat16_rn(kv.z);
            Ks[kb + 3][d] = __float2bfloat16_rn(kv.w);
            float4 vv = *(const float4*)(vp + (size_t)d * HW + m0 + kb);
            *(unsigned*)&Vs[d][kb] = pack_bf16(vv.x, vv.y);
            *(unsigned*)&Vs[d][kb + 2] = pack_bf16(vv.z, vv.w);
        }
        __syncthreads();

        float sc[8][4];
#pragma unroll
        for (int j = 0; j < 8; j++)
#pragma unroll
            for (int r = 0; r < 4; r++) sc[j][r] = 0.f;
#pragma unroll
        for (int t = 0; t < 2; t++) {
#pragma unroll
            for (int j = 0; j < 8; j++) {
                unsigned b0 = *(const unsigned*)&Ks[j * 8 + lq][t * 16 + 2 * l4];
                unsigned b1 = *(const unsigned*)&Ks[j * 8 + lq][t * 16 + 2 * l4 + 8];
                mma_bf16(sc[j], aQ[t][0], aQ[t][1], aQ[t][2], aQ[t][3], b0, b1);
            }
        }

        float mx0 = -1e30f, mx1 = -1e30f;
#pragma unroll
        for (int j = 0; j < 8; j++) {
            mx0 = fmaxf(mx0, fmaxf(sc[j][0], sc[j][1]));
            mx1 = fmaxf(mx1, fmaxf(sc[j][2], sc[j][3]));
        }
        mx0 = fmaxf(mx0, __shfl_xor_sync(0xffffffffu, mx0, 1));
        mx0 = fmaxf(mx0, __shfl_xor_sync(0xffffffffu, mx0, 2));
        mx1 = fmaxf(mx1, __shfl_xor_sync(0xffffffffu, mx1, 1));
        mx1 = fmaxf(mx1, __shfl_xor_sync(0xffffffffu, mx1, 2));

        const float nm0 = fmaxf(m0run, mx0);
        const float nm1 = fmaxf(m1run, mx1);
        const float al0 = ex2(m0run - nm0);
        const float al1 = ex2(m1run - nm1);
        m0run = nm0; m1run = nm1;

        unsigned pa01[8], pa23[8];
        float ls0 = 0.f, ls1 = 0.f;
#pragma unroll
        for (int j = 0; j < 8; j++) {
            const float p0 = ex2(sc[j][0] - nm0);
            const float p1 = ex2(sc[j][1] - nm0);
            const float p2 = ex2(sc[j][2] - nm1);
            const float p3 = ex2(sc[j][3] - nm1);
            ls0 += p0 + p1;
            ls1 += p2 + p3;
            pa01[j] = pack_bf16(p0, p1);
            pa23[j] = pack_bf16(p2, p3);
        }
        ls0 += __shfl_xor_sync(0xffffffffu, ls0, 1);
        ls0 += __shfl_xor_sync(0xffffffffu, ls0, 2);
        ls1 += __shfl_xor_sync(0xffffffffu, ls1, 1);
        ls1 += __shfl_xor_sync(0xffffffffu, ls1, 2);
        l0run = l0run * al0 + ls0;
        l1run = l1run * al1 + ls1;

#pragma unroll
        for (int j = 0; j < 4; j++) {
            oacc[j][0] *= al0; oacc[j][1] *= al0;
            oacc[j][2] *= al1; oacc[j][3] *= al1;
        }

#pragma unroll
        for (int t = 0; t < 4; t++) {
            const unsigned a0 = pa01[2 * t];
            const unsigned a1 = pa23[2 * t];
            const unsigned a2 = pa01[2 * t + 1];
            const unsigned a3 = pa23[2 * t + 1];
#pragma unroll
            for (int j = 0; j < 4; j++) {
                unsigned b0 = *(const unsigned*)&Vs[j * 8 + lq][t * 16 + 2 * l4];
                unsigned b1 = *(const unsigned*)&Vs[j * 8 + lq][t * 16 + 2 * l4 + 8];
                mma_bf16(oacc[j], a0, a1, a2, a3, b0, b1);
            }
        }
    }

    __syncthreads();
    const float inv0 = 1.f / l0run;
    const float inv1 = 1.f / l1run;
#pragma unroll
    for (int j = 0; j < 4; j++) {
        const int d = j * 8 + 2 * l4;
        Of[d][q0] = oacc[j][0] * inv0;
        Of[d + 1][q0] = oacc[j][1] * inv0;
        Of[d][q0 + 8] = oacc[j][2] * inv1;
        Of[d + 1][q0 + 8] = oacc[j][3] * inv1;
    }
    __syncthreads();

    float* aob = g_ao + ((size_t)b * CC + h * HD) * HW;
#pragma unroll
    for (int t = 0; t < 4; t++) {
        const int i = tid + t * 128;
        const int d = i >> 4, q4 = (i & 15) * 4;
        float4 v = *(const float4*)&Of[d][q4];
        *(float4*)(aob + (size_t)d * HW + n0q + q4) = v;
    }
}

// ---------------------------------------------------------------------------
extern "C" void kernel_launch(void* const* d_in, const int* in_sizes, int n_in,
                              void* d_out, int out_size) {
    const float* x = (const float*)d_in[0];
    const float* gn_scale = (const float*)d_in[1];
    const float* gn_bias = (const float*)d_in[2];
    const float* w_qkv = (const float*)d_in[3];
    const float* b_qkv = (const float*)d_in[4];
    const float* w_out = (const float*)d_in[5];
    const float* b_out = (const float*)d_in[6];
    float* out = (float*)d_out;

    float* hbuf; cudaGetSymbolAddress((void**)&hbuf, g_h);
    float* qkv;  cudaGetSymbolAddress((void**)&qkv, g_qkv);
    float* ao;   cudaGetSymbolAddress((void**)&ao, g_ao);

    gn_kernel<<<BB * NG, 256>>>(x, gn_scale, gn_bias);

    {
        dim3 grid(HW / 128, (3 * CC) / 128, BB);   // 8 x 6 x 8
        gemm_tc2<3 * CC, false><<<grid, 256>>>(w_qkv, b_qkv, hbuf, nullptr, qkv);
    }

    attn_bf16<<<BB * HEADS * 16, 128>>>();

    {
        dim3 grid(HW / 128, CC / 128, BB);         // 8 x 2 x 8
        gemm_tc2<CC, true><<<grid, 256>>>(w_out, b_out, ao, x, out);
    }
}